// round 14
// baseline (speedup 1.0000x reference)
#include <cuda_runtime.h>
#include <cstdint>

#define ROWS_T   1048576
#define BINS     17
#define GROUPS   262144
#define TPB      128                // 4 warps -> all 4 SMSPs
#define GPB      64                 // groups per chunk (2 threads per group)
#define FPG      68
#define CHUNKS   (GROUPS / GPB)     // 4096
#define CONVN    33
#define SLAB     (GPB * FPG)        // 4352 floats per tensor
#define CHUNK_BYTES (SLAB * 4)      // 17408
#define SCRATCHN (GPB * CONVN)      // 2112 floats (output block per chunk)
#define SCRATCHA (SCRATCHN + 4)     // +1 shift pad, rounded
#define GRID     760                // 152 SMs * 5 resident CTAs
#define SMEM_BYTES ((2 * SLAB + SCRATCHA) * 4)

typedef unsigned long long ull;

__device__ float2 g_part[GRID];
__device__ int    g_done = 0;

// ---- fast math ----
__device__ __forceinline__ float fast_ex2(float x) {
    float r; asm("ex2.approx.ftz.f32 %0, %1;" : "=f"(r) : "f"(x)); return r;
}
__device__ __forceinline__ float fast_lg2(float x) {
    float r; asm("lg2.approx.ftz.f32 %0, %1;" : "=f"(r) : "f"(x)); return r;
}
__device__ __forceinline__ float fast_rcp(float x) {
    float r; asm("rcp.approx.ftz.f32 %0, %1;" : "=f"(r) : "f"(x)); return r;
}
__device__ __forceinline__ ull pack2(float lo, float hi) {
    ull r; asm("mov.b64 %0, {%1, %2};" : "=l"(r) : "f"(lo), "f"(hi)); return r;
}
__device__ __forceinline__ void unpack2(ull v, float& lo, float& hi) {
    asm("mov.b64 {%0, %1}, %2;" : "=f"(lo), "=f"(hi) : "l"(v));
}
__device__ __forceinline__ ull ffma2(ull a, ull b, ull c) {
    ull d; asm("fma.rn.f32x2 %0, %1, %2, %3;" : "=l"(d) : "l"(a), "l"(b), "l"(c));
    return d;
}
__device__ __forceinline__ ull fadd2(ull a, ull b) {
    ull d; asm("add.rn.f32x2 %0, %1, %2;" : "=l"(d) : "l"(a), "l"(b));
    return d;
}

// ---- TMA / mbarrier ----
__device__ __forceinline__ uint32_t smem_u32(const void* p) {
    return (uint32_t)__cvta_generic_to_shared(p);
}
__device__ __forceinline__ void mbar_init(uint32_t a, uint32_t cnt) {
    asm volatile("mbarrier.init.shared.b64 [%0], %1;" :: "r"(a), "r"(cnt) : "memory");
}
__device__ __forceinline__ void mbar_expect_tx(uint32_t a, uint32_t bytes) {
    asm volatile("mbarrier.arrive.expect_tx.shared.b64 _, [%0], %1;"
                 :: "r"(a), "r"(bytes) : "memory");
}
__device__ __forceinline__ void bulk_g2s(uint32_t dst, const void* src,
                                         uint32_t bytes, uint32_t mbar) {
    asm volatile("cp.async.bulk.shared::cta.global.mbarrier::complete_tx::bytes "
                 "[%0], [%1], %2, [%3];"
                 :: "r"(dst), "l"(src), "r"(bytes), "r"(mbar) : "memory");
}
__device__ __forceinline__ void fence_proxy_async_shared() {
    asm volatile("fence.proxy.async.shared::cta;" ::: "memory");
}
__device__ __forceinline__ void mbar_wait(uint32_t mbar, uint32_t parity) {
    uint32_t done;
    asm volatile(
        "{\n\t.reg .pred p;\n\t"
        "mbarrier.try_wait.parity.acquire.cta.shared::cta.b64 p, [%1], %2;\n\t"
        "selp.b32 %0, 1, 0, p;\n\t}"
        : "=r"(done) : "r"(mbar), "r"(parity) : "memory");
    if (!done) {
        asm volatile(
            "{\n\t.reg .pred P1;\n\t"
            "WL_%=:\n\t"
            "mbarrier.try_wait.parity.acquire.cta.shared::cta.b64 P1, [%0], %1, 0x989680;\n\t"
            "@P1 bra.uni WD_%=;\n\t"
            "bra.uni WL_%=;\n\t"
            "WD_%=:\n\t}"
            :: "r"(mbar), "r"(parity) : "memory");
    }
}

#define LOG2E 1.4426950408889634f
#define LN2   0.6931471805599453f

// One row, with precomputed sum (s*) and sum-of-squares (q*).
// er[17] = exp(y_j) raw numerators, *invOut = 1/sum.
__device__ __forceinline__ float process_row(const float* __restrict__ x,
                                             const float* __restrict__ y,
                                             float sx, float qx,
                                             float sy, float qy,
                                             float* __restrict__ er,
                                             float* __restrict__ invOut) {
    float mux = sx * (1.0f / 17.0f);
    float vx  = fmaf(-17.0f * mux, mux, qx) * (1.0f / 16.0f);
    float isx = 0.1f * fast_rcp(1e-7f + sqrtf(vx));
    float kx  = isx * LOG2E;
    float bxc = mux * kx;
    float e0 = 0.f, e1 = 0.f;
#pragma unroll
    for (int j = 0; j < BINS; j += 2) e0 += fast_ex2(fmaf(x[j], kx, -bxc));
#pragma unroll
    for (int j = 1; j < BINS; j += 2) e1 += fast_ex2(fmaf(x[j], kx, -bxc));
    float lses = LN2 * fast_lg2(e0 + e1);

    float muy = sy * (1.0f / 17.0f);
    float vy  = fmaf(-17.0f * muy, muy, qy) * (1.0f / 16.0f);
    float isy = 0.1f * fast_rcp(1e-7f + sqrtf(vy));
    float ky  = isy * LOG2E;
    float byc = muy * ky;

    float Et = 0.f, E2 = 0.f, dx = 0.f, dy = 0.f;
#pragma unroll
    for (int j = 0; j < BINS; j++) {
        float e = fast_ex2(fmaf(y[j], ky, -byc));
        Et += e;
        dx = fmaf(e, x[j], dx);
        dy = fmaf(e, y[j], dy);
        float r = fast_ex2(y[j] * LOG2E);
        E2 += r;
        er[j] = r;
    }
    *invOut = fast_rcp(E2);

    float invEt = fast_rcp(Et);
    float lset  = LN2 * fast_lg2(Et);

    return (dy * invEt - muy) * isy - lset
         - (dx * invEt - mux) * isx + lses;
}

__global__ __launch_bounds__(TPB, 5)
void kd_main(const char* __restrict__ pred_b,
             const char* __restrict__ soft_b,
             const float4* __restrict__ w4,
             float* __restrict__ out) {
    extern __shared__ float dyn[];     // sp[SLAB] | ss[SLAB] | scratch[SCRATCHA]
    __shared__ float  red[8];
    __shared__ double dred[8];
    __shared__ int    s_last;
    __shared__ __align__(8) ull mbar_store;

    const int tid = threadIdx.x;
    const uint32_t mb    = smem_u32(&mbar_store);
    const uint32_t sp_a  = smem_u32(dyn);
    const uint32_t ss_a  = sp_a + CHUNK_BYTES;

    float* sp = dyn;
    float* ss = dyn + SLAB;
    float* sc = dyn + 2 * SLAB;        // 16B-aligned (2*SLAB*4 = 34816)

    if (tid == 0) {
        mbar_init(mb, 1);
        fence_proxy_async_shared();
    }
    __syncthreads();

    int c = blockIdx.x;
    uint32_t par = 0;

    if (tid == 0) {                    // prologue: fetch first chunk
        mbar_expect_tx(mb, 2 * CHUNK_BYTES);
        bulk_g2s(sp_a, pred_b + (size_t)c * CHUNK_BYTES, CHUNK_BYTES, mb);
        bulk_g2s(ss_a, soft_b + (size_t)c * CHUNK_BYTES, CHUNK_BYTES, mb);
    }

    const int g   = tid >> 1;
    const int hh  = tid & 1;           // 0 -> rows 0,1 (tb); 1 -> rows 2,3 (lr)
    const int off = g * FPG + hh * 34;

    float kl_acc = 0.f, w_acc = 0.f;

    for (; c < CHUNKS; c += GRID) {
        mbar_wait(mb, par); par ^= 1;

        // ---- slab -> registers (float2) with FUSED packed f32x2 stats.
        //      lo/hi lanes = even/odd elements; m==8 straddles rows, scalar. ----
        float bx[34], by[34];
        ull Sx0 = 0, Qx0 = 0, Sx1 = 0, Qx1 = 0;
        ull Sy0 = 0, Qy0 = 0, Sy1 = 0, Qy1 = 0;
        {
            const float2* p2 = reinterpret_cast<const float2*>(sp + off);
            const float2* q2 = reinterpret_cast<const float2*>(ss + off);
#pragma unroll
            for (int m = 0; m < 17; m++) {
                float2 a = p2[m]; bx[2 * m] = a.x; bx[2 * m + 1] = a.y;
                float2 b = q2[m]; by[2 * m] = b.x; by[2 * m + 1] = b.y;
                ull au = pack2(a.x, a.y);
                ull bu = pack2(b.x, b.y);
                if (m < 8) {
                    Sx0 = fadd2(Sx0, au); Qx0 = ffma2(au, au, Qx0);
                    Sy0 = fadd2(Sy0, bu); Qy0 = ffma2(bu, bu, Qy0);
                } else if (m > 8) {
                    Sx1 = fadd2(Sx1, au); Qx1 = ffma2(au, au, Qx1);
                    Sy1 = fadd2(Sy1, bu); Qy1 = ffma2(bu, bu, Qy1);
                }
            }
        }
        __syncthreads();               // all slab reads + prev out-store done

        // ---- prefetch next chunk into the SAME buffers (overlaps compute) ----
        const int cn = c + GRID;
        if (tid == 0 && cn < CHUNKS) {
            fence_proxy_async_shared();
            mbar_expect_tx(mb, 2 * CHUNK_BYTES);
            bulk_g2s(sp_a, pred_b + (size_t)cn * CHUNK_BYTES, CHUNK_BYTES, mb);
            bulk_g2s(ss_a, soft_b + (size_t)cn * CHUNK_BYTES, CHUNK_BYTES, mb);
        }

        // ---- horizontal stat reduction (+ row-straddle fixup) ----
        float lo, hi;
        unpack2(Sx0, lo, hi); float sxa = lo + hi + bx[16];
        unpack2(Qx0, lo, hi); float qxa = fmaf(bx[16], bx[16], lo + hi);
        unpack2(Sx1, lo, hi); float sxb = lo + hi + bx[17];
        unpack2(Qx1, lo, hi); float qxb = fmaf(bx[17], bx[17], lo + hi);
        unpack2(Sy0, lo, hi); float sya = lo + hi + by[16];
        unpack2(Qy0, lo, hi); float qya = fmaf(by[16], by[16], lo + hi);
        unpack2(Sy1, lo, hi); float syb = lo + hi + by[17];
        unpack2(Qy1, lo, hi); float qyb = fmaf(by[17], by[17], lo + hi);

        float t0[BINS], t1[BINS];
        float inv0, inv1;
        kl_acc += process_row(bx,      by,      sxa, qxa, sya, qya, t0, &inv0);
        kl_acc += process_row(bx + 17, by + 17, sxb, qxb, syb, qyb, t1, &inv1);

        // ---- convolution: packed FFMA2 even i, scalar FFMA odd i ----
        const float cc = inv0 * inv1;
        ull t1p[9], P[17];
#pragma unroll
        for (int q = 0; q < 17; q++) P[q] = 0ULL;
#pragma unroll
        for (int m = 0; m < 8; m++) t1p[m] = pack2(t1[2 * m], t1[2 * m + 1]);
        t1p[8] = pack2(t1[16], 0.f);

#pragma unroll
        for (int ie = 0; ie < 9; ie++) {
            float a = t0[2 * ie] * cc;
            ull A = pack2(a, a);
#pragma unroll
            for (int m = 0; m < 9; m++) P[ie + m] = ffma2(A, t1p[m], P[ie + m]);
        }

        float conv[CONVN + 1];
#pragma unroll
        for (int q = 0; q < 17; q++)
            unpack2(P[q], conv[2 * q], conv[2 * q + 1]);

#pragma unroll
        for (int io = 0; io < 8; io++) {
            float a = t0[2 * io + 1] * cc;
#pragma unroll
            for (int j = 0; j < BINS; j++)
                conv[2 * io + 1 + j] = fmaf(a, t1[j], conv[2 * io + 1 + j]);
        }

        // ---- weight (even lanes: 4 rows' weights per group) ----
        if (!hh) {
            float4 w = w4[(size_t)c * GPB + g];
            w_acc += (w.x + w.y) + (w.z + w.w);
        }

        // ---- split ratio into scratch (+1 shift for epilogue alignment) ----
        {
            float* scb = sc + 1 + g * CONVN + (hh ? 16 : 0);
#pragma unroll
            for (int m = 0; m < 17; m++) {
                float send = hh ? conv[m] : conv[m + 16];
                float v    = __shfl_xor_sync(0xffffffffu, send, 1);
                float num  = hh ? conv[m + 16] : v;
                float den  = (hh ? v : conv[m]) + 1e-8f;
                scb[m] = num * fast_rcp(den);
            }
        }

        __syncthreads();               // scratch visible

        // ---- vectorized output: head(3) + 527x float4 + tail(1) ----
        size_t obase = 1 + (size_t)c * SCRATCHN;
        if (tid < 3) out[obase + tid] = sc[1 + tid];
        {
            const float4* v4 = reinterpret_cast<const float4*>(sc + 4);
            float4* o4 = reinterpret_cast<float4*>(out + obase + 3);
#pragma unroll
            for (int k = 0; k < 5; k++) {
                int i = tid + k * TPB;
                if (i < 527) o4[i] = v4[i];
            }
        }
        if (tid == 3) out[obase + 2111] = sc[2112];
    }

    // ---- one block reduction at exit ----
    float v0 = kl_acc, v1 = w_acc;
#pragma unroll
    for (int o = 16; o > 0; o >>= 1) {
        v0 += __shfl_down_sync(0xffffffffu, v0, o);
        v1 += __shfl_down_sync(0xffffffffu, v1, o);
    }
    if ((tid & 31) == 0) {
        red[(tid >> 5) * 2]     = v0;
        red[(tid >> 5) * 2 + 1] = v1;
    }
    __syncthreads();
    if (tid == 0) {
        g_part[blockIdx.x] = make_float2(red[0] + red[2] + red[4] + red[6],
                                         red[1] + red[3] + red[5] + red[7]);
        __threadfence();
        int d = atomicAdd(&g_done, 1);
        s_last = (d == GRID - 1);
    }
    __syncthreads();

    // ---- last block: scalar loss over 760 block partials ----
    if (s_last) {
        __threadfence();
        double s0 = 0.0, s1 = 0.0;
        for (int i = tid; i < GRID; i += TPB) {
            float2 p = g_part[i];
            s0 += (double)p.x; s1 += (double)p.y;
        }
#pragma unroll
        for (int o = 16; o > 0; o >>= 1) {
            s0 += __shfl_down_sync(0xffffffffu, s0, o);
            s1 += __shfl_down_sync(0xffffffffu, s1, o);
        }
        if ((tid & 31) == 0) {
            dred[(tid >> 5) * 2]     = s0;
            dred[(tid >> 5) * 2 + 1] = s1;
        }
        __syncthreads();
        if (tid == 0) {
            double S0 = dred[0] + dred[2] + dred[4] + dred[6];
            double S1 = dred[1] + dred[3] + dred[5] + dred[7];
            out[0] = (float)((S0 / (double)ROWS_T) * 100.0 * (S1 / (double)ROWS_T));
            g_done = 0;    // reset for next graph replay
        }
    }
}

extern "C" void kernel_launch(void* const* d_in, const int* in_sizes, int n_in,
                              void* d_out, int out_size) {
    const char* pred  = (const char*)d_in[0];
    const char* soft  = (const char*)d_in[1];
    const float4* w   = (const float4*)d_in[2];
    float* out = (float*)d_out;

    static int attr_set = 0;
    if (!attr_set) {
        cudaFuncSetAttribute(kd_main, cudaFuncAttributeMaxDynamicSharedMemorySize,
                             SMEM_BYTES);
        attr_set = 1;
    }
    kd_main<<<GRID, TPB, SMEM_BYTES>>>(pred, soft, w, out);
}